// round 5
// baseline (speedup 1.0000x reference)
#include <cuda_runtime.h>
#include <cstdint>

#define E_TOT  43234
#define NTILES 1352            // ceil(E_TOT/32)

// Rotated+NEGATED head: g_head[b*512 + q*8 + {0..3}] = -re(4q..4q+3), {4..7} = -im(4q..4q+3)
__device__ float g_head[32 * 512];

// ---------- f32x2 packed helpers (sm_103a) ----------
static __device__ __forceinline__ unsigned long long addx2(unsigned long long a, unsigned long long b) {
    unsigned long long r; asm("add.rn.f32x2 %0, %1, %2;" : "=l"(r) : "l"(a), "l"(b)); return r;
}
static __device__ __forceinline__ unsigned long long mulx2(unsigned long long a, unsigned long long b) {
    unsigned long long r; asm("mul.rn.f32x2 %0, %1, %2;" : "=l"(r) : "l"(a), "l"(b)); return r;
}
static __device__ __forceinline__ unsigned long long fmax2(unsigned long long a, unsigned long long b, unsigned long long c) {
    unsigned long long r; asm("fma.rn.f32x2 %0, %1, %2, %3;" : "=l"(r) : "l"(a), "l"(b), "l"(c)); return r;
}
static __device__ __forceinline__ void unpack2(unsigned long long v, float& lo, float& hi) {
    asm("mov.b64 {%0, %1}, %2;" : "=f"(lo), "=f"(hi) : "l"(v));
}
static __device__ __forceinline__ float sqrt_approx(float x) {
    float r; asm("sqrt.approx.f32 %0, %1;" : "=f"(r) : "f"(x)); return r;
}
// 16B loads: entity with .cg (bypass L1 -> keep head table L1-resident), head with .nc (L1-cached)
static __device__ __forceinline__ void ldcg_u2(const void* p, unsigned long long& x, unsigned long long& y) {
    asm("ld.global.cg.v2.u64 {%0, %1}, [%2];" : "=l"(x), "=l"(y) : "l"(p));
}
static __device__ __forceinline__ void ldnc_u2(const void* p, unsigned long long& x, unsigned long long& y) {
    asm("ld.global.nc.v2.u64 {%0, %1}, [%2];" : "=l"(x), "=l"(y) : "l"(p));
}

// ---------- prep: rotate head, negate, broadcast-friendly layout ----------
__global__ void prep_kernel(const float* __restrict__ head, const float* __restrict__ rel) {
    int b = blockIdx.x, d = threadIdx.x;
    float re_h = head[b * 512 + d];
    float im_h = head[b * 512 + 256 + d];
    float phase = rel[b * 256 + d] * 100.53096491487338f;  // rel * 32*pi
    float s, c; sincosf(phase, &s, &c);
    float re_rot = re_h * c - im_h * s;
    float im_rot = re_h * s + im_h * c;
    int q = d >> 2, j = d & 3;
    g_head[b * 512 + q * 8 + j]     = -re_rot;
    g_head[b * 512 + q * 8 + 4 + j] = -im_rot;
}

// ---------- main: 1 warp per CTA, CTA = 32-entity tile, lane = entity, bb over all 32 b ----------
__global__ void __launch_bounds__(32)
dist_kernel(const float* __restrict__ ent, float* __restrict__ out) {
    const int lane = threadIdx.x;
    int e0 = blockIdx.x * 32;
    if (e0 > E_TOT - 32) e0 = E_TOT - 32;   // clamped tail: overlap rewrites identical values

    // this lane's entity row: re quads at ep[q], im quads at ep[64+q]  (16B units)
    const char* ep = reinterpret_cast<const char*>(ent) + (size_t)(e0 + lane) * 2048;
    const char* hp = reinterpret_cast<const char*>(g_head);  // head quads: b*2048 + q*32 (+16 for im)

    float acc[32];
#pragma unroll
    for (int bb = 0; bb < 32; bb++) acc[bb] = 0.0f;

    unsigned long long creX, creY, cimX, cimY, nreX, nreY, nimX, nimY;
    ldcg_u2(ep,        creX, creY);     // re quad q=0
    ldcg_u2(ep + 1024, cimX, cimY);     // im quad q=0

    for (int q = 0; q < 64; q++) {
        // prefetch next q's entity quads (clamped; discarded on last iter)
        const int qn = (q < 63) ? (q + 1) : 0;
        ldcg_u2(ep + qn * 16,        nreX, nreY);
        ldcg_u2(ep + 1024 + qn * 16, nimX, nimY);

        const char* hq = hp + q * 32;
#pragma unroll
        for (int bb = 0; bb < 32; bb++) {
            unsigned long long hreX, hreY, himX, himY;
            ldnc_u2(hq + bb * 2048,      hreX, hreY);   // -rot re quad (warp-uniform, L1-hit)
            ldnc_u2(hq + bb * 2048 + 16, himX, himY);   // -rot im quad

            unsigned long long a0 = addx2(creX, hreX);  // t_re - rot_re, d pair {4q,4q+1}
            unsigned long long a1 = addx2(creY, hreY);  // d pair {4q+2,4q+3}
            unsigned long long c0 = addx2(cimX, himX);
            unsigned long long c1 = addx2(cimY, himY);
            unsigned long long p0 = fmax2(c0, c0, mulx2(a0, a0));
            unsigned long long p1 = fmax2(c1, c1, mulx2(a1, a1));

            float x0, x1, y0, y1;
            unpack2(p0, x0, x1);
            unpack2(p1, y0, y1);
            acc[bb] += (sqrt_approx(x0) + sqrt_approx(x1)) + (sqrt_approx(y0) + sqrt_approx(y1));
        }

        creX = nreX; creY = nreY; cimX = nimX; cimY = nimY;
    }

    // 32 coalesced row stores
#pragma unroll
    for (int bb = 0; bb < 32; bb++)
        out[(size_t)bb * E_TOT + e0 + lane] = 6.0f - acc[bb];
}

extern "C" void kernel_launch(void* const* d_in, const int* in_sizes, int n_in,
                              void* d_out, int out_size) {
    const float* head = (const float*)d_in[0];   // (32, 512)
    const float* rel  = (const float*)d_in[1];   // (32, 256)
    const float* ent  = (const float*)d_in[2];   // (43234, 512)
    float* out = (float*)d_out;                  // (32, 43234)

    prep_kernel<<<32, 256>>>(head, rel);
    dist_kernel<<<NTILES, 32>>>(ent, out);
}

// round 6
// speedup vs baseline: 1.1469x; 1.1469x over previous
#include <cuda_runtime.h>
#include <cstdint>

#define E_TOT  43234
#define NTILES 1352            // ceil(E_TOT/32)
#define NCTA   676             // 2 tiles per CTA

// Rotated+NEGATED head: g_head[b*512 + q*8 + {0..3}] = -re(4q..4q+3), {4..7} = -im(4q..4q+3)
__device__ float g_head[32 * 512];

// ---------- f32x2 packed helpers (sm_103a) ----------
static __device__ __forceinline__ unsigned long long addx2(unsigned long long a, unsigned long long b) {
    unsigned long long r; asm("add.rn.f32x2 %0, %1, %2;" : "=l"(r) : "l"(a), "l"(b)); return r;
}
static __device__ __forceinline__ unsigned long long mulx2(unsigned long long a, unsigned long long b) {
    unsigned long long r; asm("mul.rn.f32x2 %0, %1, %2;" : "=l"(r) : "l"(a), "l"(b)); return r;
}
static __device__ __forceinline__ unsigned long long fmax2(unsigned long long a, unsigned long long b, unsigned long long c) {
    unsigned long long r; asm("fma.rn.f32x2 %0, %1, %2, %3;" : "=l"(r) : "l"(a), "l"(b), "l"(c)); return r;
}
static __device__ __forceinline__ void unpack2(unsigned long long v, float& lo, float& hi) {
    asm("mov.b64 {%0, %1}, %2;" : "=f"(lo), "=f"(hi) : "l"(v));
}
static __device__ __forceinline__ float sqrt_approx(float x) {
    float r; asm("sqrt.approx.f32 %0, %1;" : "=f"(r) : "f"(x)); return r;
}
// entity: .cg (L2 only — keep L1 for the head table). head: .nc (L1-resident broadcast)
static __device__ __forceinline__ void ldcg_u2(const void* p, unsigned long long& x, unsigned long long& y) {
    asm("ld.global.cg.v2.u64 {%0, %1}, [%2];" : "=l"(x), "=l"(y) : "l"(p));
}
static __device__ __forceinline__ void ldnc_u2(const void* p, unsigned long long& x, unsigned long long& y) {
    asm("ld.global.nc.v2.u64 {%0, %1}, [%2];" : "=l"(x), "=l"(y) : "l"(p));
}

// ---------- prep: rotate head, negate, broadcast-friendly layout ----------
__global__ void prep_kernel(const float* __restrict__ head, const float* __restrict__ rel) {
    int b = blockIdx.x, d = threadIdx.x;
    float re_h = head[b * 512 + d];
    float im_h = head[b * 512 + 256 + d];
    float phase = rel[b * 256 + d] * 100.53096491487338f;  // rel * 32*pi
    float s, c; sincosf(phase, &s, &c);
    float re_rot = re_h * c - im_h * s;
    float im_rot = re_h * s + im_h * c;
    int q = d >> 2, j = d & 3;
    g_head[b * 512 + q * 8 + j]     = -re_rot;
    g_head[b * 512 + q * 8 + 4 + j] = -im_rot;
}

// ---------- main: 8 warps/CTA = 2 tiles x 4 b-groups; lane = entity, warp covers 8 b ----------
__global__ void __launch_bounds__(256, 3)
dist_kernel(const float* __restrict__ ent, float* __restrict__ out) {
    const int lane = threadIdx.x & 31;
    const int wid  = threadIdx.x >> 5;
    const int bg   = (wid & 3) * 8;            // first b of this warp's 8-b group

    int e0 = (blockIdx.x * 2 + (wid >> 2)) * 32;
    if (e0 > E_TOT - 32) e0 = E_TOT - 32;      // clamped tail: overlap rewrites identical values

    // this lane's entity row: re quads at +q*16, im quads at +1024+q*16
    const char* ep = reinterpret_cast<const char*>(ent) + (size_t)(e0 + lane) * 2048;
    const char* hp = reinterpret_cast<const char*>(g_head) + (size_t)bg * 2048;  // head quads: bb*2048 + q*32 (+16 im)

    float acc[8];
#pragma unroll
    for (int bb = 0; bb < 8; bb++) acc[bb] = 0.0f;

    unsigned long long creX, creY, cimX, cimY, nreX, nreY, nimX, nimY;
    ldcg_u2(ep,        creX, creY);
    ldcg_u2(ep + 1024, cimX, cimY);

    for (int q = 0; q < 64; q++) {
        // prefetch next q's entity quads (wraps to 0 on last iter; discarded)
        const int qn = (q < 63) ? (q + 1) : 0;
        ldcg_u2(ep + qn * 16,        nreX, nreY);
        ldcg_u2(ep + 1024 + qn * 16, nimX, nimY);

        const char* hq = hp + q * 32;
#pragma unroll
        for (int bb = 0; bb < 8; bb++) {
            unsigned long long hreX, hreY, himX, himY;
            ldnc_u2(hq + bb * 2048,      hreX, hreY);   // -rot re quad (uniform, L1-hit, 1 wf)
            ldnc_u2(hq + bb * 2048 + 16, himX, himY);   // -rot im quad

            unsigned long long a0 = addx2(creX, hreX);  // t_re - rot_re, pair {4q,4q+1}
            unsigned long long a1 = addx2(creY, hreY);  // pair {4q+2,4q+3}
            unsigned long long c0 = addx2(cimX, himX);
            unsigned long long c1 = addx2(cimY, himY);
            unsigned long long p0 = fmax2(c0, c0, mulx2(a0, a0));
            unsigned long long p1 = fmax2(c1, c1, mulx2(a1, a1));

            float x0, x1, y0, y1;
            unpack2(p0, x0, x1);
            unpack2(p1, y0, y1);
            acc[bb] += (sqrt_approx(x0) + sqrt_approx(x1)) + (sqrt_approx(y0) + sqrt_approx(y1));
        }

        creX = nreX; creY = nreY; cimX = nimX; cimY = nimY;
    }

    // 8 coalesced row stores (128B per warp-store)
#pragma unroll
    for (int bb = 0; bb < 8; bb++)
        out[(size_t)(bg + bb) * E_TOT + e0 + lane] = 6.0f - acc[bb];
}

extern "C" void kernel_launch(void* const* d_in, const int* in_sizes, int n_in,
                              void* d_out, int out_size) {
    const float* head = (const float*)d_in[0];   // (32, 512)
    const float* rel  = (const float*)d_in[1];   // (32, 256)
    const float* ent  = (const float*)d_in[2];   // (43234, 512)
    float* out = (float*)d_out;                  // (32, 43234)

    prep_kernel<<<32, 256>>>(head, rel);
    dist_kernel<<<NCTA, 256>>>(ent, out);
}

// round 7
// speedup vs baseline: 1.3094x; 1.1418x over previous
#include <cuda_runtime.h>
#include <cuda_fp16.h>
#include <cstdint>

#define E_TOT   43234
#define ET      4
#define NWTILE  10809          // ceil(E_TOT/ET)
#define NCTA    444            // 3 CTA/SM * 148
#define NTHR    256
#define TOTW    (NCTA * (NTHR / 32))

// fp16 rotated+NEGATED head: g_head16[(q*32 + b)*8 + {0..3}] = -re(4q..4q+3), {4..7} = -im
__device__ __half g_head16[64 * 32 * 8];   // 32 KB

// ---------- f32x2 packed helpers (sm_103a) ----------
static __device__ __forceinline__ unsigned long long addx2(unsigned long long a, unsigned long long b) {
    unsigned long long r; asm("add.rn.f32x2 %0, %1, %2;" : "=l"(r) : "l"(a), "l"(b)); return r;
}
static __device__ __forceinline__ unsigned long long mulx2(unsigned long long a, unsigned long long b) {
    unsigned long long r; asm("mul.rn.f32x2 %0, %1, %2;" : "=l"(r) : "l"(a), "l"(b)); return r;
}
static __device__ __forceinline__ unsigned long long fmax2(unsigned long long a, unsigned long long b, unsigned long long c) {
    unsigned long long r; asm("fma.rn.f32x2 %0, %1, %2, %3;" : "=l"(r) : "l"(a), "l"(b), "l"(c)); return r;
}
static __device__ __forceinline__ void unpack2(unsigned long long v, float& lo, float& hi) {
    asm("mov.b64 {%0, %1}, %2;" : "=f"(lo), "=f"(hi) : "l"(v));
}
static __device__ __forceinline__ unsigned long long packf2(float2 f) {
    unsigned long long r; asm("mov.b64 %0, {%1, %2};" : "=l"(r) : "f"(f.x), "f"(f.y)); return r;
}
static __device__ __forceinline__ float sqrt_approx(float x) {
    float r; asm("sqrt.approx.f32 %0, %1;" : "=f"(r) : "f"(x)); return r;
}

// ---------- prep: rotate head, negate, quantize to fp16, transposed layout ----------
__global__ void prep_kernel(const float* __restrict__ head, const float* __restrict__ rel) {
    int b = blockIdx.x, d = threadIdx.x;
    float re_h = head[b * 512 + d];
    float im_h = head[b * 512 + 256 + d];
    float phase = rel[b * 256 + d] * 100.53096491487338f;  // rel * 32*pi
    float s, c; sincosf(phase, &s, &c);
    float re_rot = re_h * c - im_h * s;
    float im_rot = re_h * s + im_h * c;
    int q = d >> 2, j = d & 3;
    g_head16[((q * 32) + b) * 8 + j]     = __float2half(-re_rot);
    g_head16[((q * 32) + b) * 8 + 4 + j] = __float2half(-im_rot);
}

// ---------- main: lane = b, warp = 4-entity tile; fp16 head in smem (32KB) ----------
__global__ void __launch_bounds__(NTHR, 3)
dist_kernel(const float* __restrict__ ent, float* __restrict__ out) {
    __shared__ uint4 sh[64 * 32];   // sh[q*32 + b] = 8 fp16: {re quad, im quad}, 32 KB
    {
        const uint4* src = reinterpret_cast<const uint4*>(g_head16);
        for (int i = threadIdx.x; i < 64 * 32; i += NTHR) sh[i] = src[i];
    }
    __syncthreads();

    const int gw   = (blockIdx.x * NTHR + threadIdx.x) >> 5;
    const int lane = threadIdx.x & 31;
    const uint4* __restrict__ hs = sh + lane;   // hs[q*32]

    for (int tile = gw; tile < NWTILE; tile += TOTW) {
        int e0 = tile * ET;
        if (e0 > E_TOT - ET) e0 = E_TOT - ET;   // clamped tail: overlap rewrites identical values
        const ulonglong2* __restrict__ base =
            reinterpret_cast<const ulonglong2*>(ent) + (size_t)e0 * 128;
        // entity t: re quad at base[t*128 + q], im quad at base[t*128 + 64 + q]

        float acc[ET] = {0.0f, 0.0f, 0.0f, 0.0f};

#pragma unroll 2
        for (int q = 0; q < 64; q++) {
            // entity quads (warp-uniform broadcast LDG.128, L2-resident)
            ulonglong2 tre0 = __ldg(base + q);
            ulonglong2 tim0 = __ldg(base + 64 + q);
            ulonglong2 tre1 = __ldg(base + 128 + q);
            ulonglong2 tim1 = __ldg(base + 192 + q);
            ulonglong2 tre2 = __ldg(base + 256 + q);
            ulonglong2 tim2 = __ldg(base + 320 + q);
            ulonglong2 tre3 = __ldg(base + 384 + q);
            ulonglong2 tim3 = __ldg(base + 448 + q);

            // this lane's (b) head quad for d=4q..4q+3: one LDS.128, fp16 -> f32x2 pairs
            uint4 hh = hs[q * 32];
            const __half2* hp = reinterpret_cast<const __half2*>(&hh);
            unsigned long long hre0 = packf2(__half22float2(hp[0]));  // -re pair {4q,4q+1}
            unsigned long long hre1 = packf2(__half22float2(hp[1]));  // -re pair {4q+2,4q+3}
            unsigned long long him0 = packf2(__half22float2(hp[2]));
            unsigned long long him1 = packf2(__half22float2(hp[3]));

            const ulonglong2 re[ET] = {tre0, tre1, tre2, tre3};
            const ulonglong2 im[ET] = {tim0, tim1, tim2, tim3};
#pragma unroll
            for (int t = 0; t < ET; t++) {
                unsigned long long a0 = addx2(re[t].x, hre0);
                unsigned long long a1 = addx2(re[t].y, hre1);
                unsigned long long c0 = addx2(im[t].x, him0);
                unsigned long long c1 = addx2(im[t].y, him1);
                unsigned long long p0 = fmax2(c0, c0, mulx2(a0, a0));
                unsigned long long p1 = fmax2(c1, c1, mulx2(a1, a1));
                float x0, x1, y0, y1;
                unpack2(p0, x0, x1);
                unpack2(p1, y0, y1);
                acc[t] += (sqrt_approx(x0) + sqrt_approx(x1)) + (sqrt_approx(y0) + sqrt_approx(y1));
            }
        }

        float2* op = reinterpret_cast<float2*>(out + (size_t)lane * E_TOT + e0);
        op[0] = make_float2(6.0f - acc[0], 6.0f - acc[1]);
        op[1] = make_float2(6.0f - acc[2], 6.0f - acc[3]);
    }
}

extern "C" void kernel_launch(void* const* d_in, const int* in_sizes, int n_in,
                              void* d_out, int out_size) {
    const float* head = (const float*)d_in[0];   // (32, 512)
    const float* rel  = (const float*)d_in[1];   // (32, 256)
    const float* ent  = (const float*)d_in[2];   // (43234, 512)
    float* out = (float*)d_out;                  // (32, 43234)

    prep_kernel<<<32, 256>>>(head, rel);
    dist_kernel<<<NCTA, NTHR>>>(ent, out);
}